// round 1
// baseline (speedup 1.0000x reference)
#include <cuda_runtime.h>
#include <math.h>

#define N_NODES 50000
#define N_EDGES 800000
#define NB 32
#define NT 6
#define NA 128
#define AGG_ELEMS (N_NODES * NT * NB)

// scratch (static device arrays — no allocation)
__device__ float g_cj[N_NODES];
__device__ float g_agg[AGG_ELEMS];   // layout [n][t][b]

// constants matching numpy: WIDTH = float32(10/31); coeff = -0.5/WIDTH^2
__device__ __forceinline__ float coeff_const() {
    constexpr float WF  = 10.0f / 31.0f;          // correctly-rounded float(10/31)
    constexpr float W2F = WF * WF;
    constexpr double C  = -0.5 / (double)W2F;
    return (float)C;
}

__device__ __forceinline__ float silu_fast(float x) {
    return __fdividef(x, 1.0f + __expf(-x));
}

// ---------------------------------------------------------------------------
__global__ void zero_agg_kernel() {
    int i = blockIdx.x * blockDim.x + threadIdx.x;
    int stride = gridDim.x * blockDim.x;
    for (; i < AGG_ELEMS; i += stride) g_agg[i] = 0.0f;
}

// ---------------------------------------------------------------------------
// cj = silu(feat @ w1 + b1) @ w2 + b2   -> g_cj[n]
// block = 128 threads, NODES_PER_BLOCK nodes per block, w1 staged in smem
#define CJ_NPB 32
__global__ void cj_kernel(const float* __restrict__ feat,
                          const float* __restrict__ w1,
                          const float* __restrict__ b1,
                          const float* __restrict__ w2,
                          const float* __restrict__ b2,
                          int nNodes)
{
    extern __shared__ float sm[];
    float* w1s   = sm;            // 128*128
    float* b1s   = w1s + NA * NA; // 128
    float* w2s   = b1s + NA;      // 128
    float* featS = w2s + NA;      // 128
    float* red   = featS + NA;    // 4

    const int tid = threadIdx.x;
    for (int i = tid; i < NA * NA; i += blockDim.x) w1s[i] = w1[i];
    if (tid < NA) { b1s[tid] = b1[tid]; w2s[tid] = w2[tid]; }
    __syncthreads();

    const int lane = tid & 31;
    const int wid  = tid >> 5;
    const float bias2 = __ldg(b2);

    int node0 = blockIdx.x * CJ_NPB;
    for (int i = 0; i < CJ_NPB; i++) {
        int node = node0 + i;
        if (node >= nNodes) break;
        featS[tid] = feat[node * NA + tid];
        __syncthreads();

        float h = b1s[tid];
        #pragma unroll 8
        for (int k = 0; k < NA; k++)
            h = fmaf(featS[k], w1s[k * NA + tid], h);
        float p = silu_fast(h) * w2s[tid];

        #pragma unroll
        for (int off = 16; off > 0; off >>= 1)
            p += __shfl_xor_sync(0xffffffffu, p, off);
        if (lane == 0) red[wid] = p;
        __syncthreads();
        if (tid == 0)
            g_cj[node] = red[0] + red[1] + red[2] + red[3] + bias2;
        __syncthreads();
    }
}

// ---------------------------------------------------------------------------
// Edge kernel: one warp per edge, one lane per basis.
//  - scatter fij into g_agg with float atomics (skipped when gaussian underflows)
//  - compute filt output per (e, b)
__global__ void edge_kernel(const float* __restrict__ dis_vec,
                            const int*   __restrict__ src,
                            const int*   __restrict__ dst,
                            const float* __restrict__ fw1,
                            const float* __restrict__ fw2,
                            const float* __restrict__ fb2,
                            float* __restrict__ filt_out,
                            int nEdges)
{
    __shared__ float sW1[36];
    __shared__ float sW2[6];
    __shared__ float sB2;
    __shared__ float sOff[NB];

    const int tid = threadIdx.x;
    if (tid < 36) sW1[tid] = fw1[tid];
    if (tid < 6)  sW2[tid] = fw2[tid];
    if (tid == 36) sB2 = fb2[0];
    if (tid < NB) sOff[tid] = (float)((double)tid * (10.0 / 31.0));
    __syncthreads();

    const int gwarp = (blockIdx.x * blockDim.x + tid) >> 5;
    const int lane  = tid & 31;
    if (gwarp >= nEdges) return;
    const int e = gwarp;

    const float vx = __ldg(&dis_vec[3 * e + 0]);
    const float vy = __ldg(&dis_vec[3 * e + 1]);
    const float vz = __ldg(&dis_vec[3 * e + 2]);
    const int s = __ldg(&src[e]);
    const int d = __ldg(&dst[e]);
    const float c = __ldg(&g_cj[d]);

    // polynomial prefactors * PREF2
    const float x = vx + 1e-8f, y = vy + 1e-8f, z = vz + 1e-8f;
    const float SQ2 = 1.41421356237309515f;
    const float q0 = z * z;
    const float q1 = SQ2 * (y * z);
    const float q2 = y * y;
    const float q3 = SQ2 * (x * z);
    const float q4 = SQ2 * (x * y);
    const float q5 = x * x;

    // gaussian
    const float dx = vx + 1e-9f, dy = vy + 1e-9f, dz = vz + 1e-9f;
    const float dis = sqrtf(fmaf(dx, dx, fmaf(dy, dy, dz * dz)));
    const float dd = dis - sOff[lane];
    const float g0 = __expf(coeff_const() * dd * dd);

    const float ga0 = q0 * g0, ga1 = q1 * g0, ga2 = q2 * g0;
    const float ga3 = q3 * g0, ga4 = q4 * g0, ga5 = q5 * g0;

    // scatter-add fij = gauss * cj[dst] into agg[src][t][b]
    if (g0 > 1e-14f) {
        float* base = &g_agg[s * (NT * NB) + lane];
        atomicAdd(base + 0 * NB, ga0 * c);
        atomicAdd(base + 1 * NB, ga1 * c);
        atomicAdd(base + 2 * NB, ga2 * c);
        atomicAdd(base + 3 * NB, ga3 * c);
        atomicAdd(base + 4 * NB, ga4 * c);
        atomicAdd(base + 5 * NB, ga5 * c);
    }

    // filt path: gn = gauss / (||gauss + 1e-8|| + 1)
    const float v0 = ga0 + 1e-8f, v1 = ga1 + 1e-8f, v2 = ga2 + 1e-8f;
    const float v3 = ga3 + 1e-8f, v4 = ga4 + 1e-8f, v5 = ga5 + 1e-8f;
    float nn = v0 * v0;
    nn = fmaf(v1, v1, nn); nn = fmaf(v2, v2, nn);
    nn = fmaf(v3, v3, nn); nn = fmaf(v4, v4, nn); nn = fmaf(v5, v5, nn);
    const float sq  = nn * __frsqrt_rn(nn);            // sqrt(nn), nn >= 6e-16 > 0
    const float inv = __fdividef(1.0f, sq + 1.0f);

    float r = 0.0f;
    #pragma unroll
    for (int j = 0; j < 6; j++) {
        float h = ga0 * sW1[0 * 6 + j];
        h = fmaf(ga1, sW1[1 * 6 + j], h);
        h = fmaf(ga2, sW1[2 * 6 + j], h);
        h = fmaf(ga3, sW1[3 * 6 + j], h);
        h = fmaf(ga4, sW1[4 * 6 + j], h);
        h = fmaf(ga5, sW1[5 * 6 + j], h);
        h *= inv;
        r = fmaf(silu_fast(h), sW2[j], r);
    }
    filt_out[e * NB + lane] = r + sB2;
}

// ---------------------------------------------------------------------------
// msg path: f2 -> normalize -> silu(f2n @ w1 + b1) @ w2 + b2 -> out[n][128]
#define MSG_NPB 16
__global__ void msg_kernel(const float* __restrict__ w1,
                           const float* __restrict__ b1,
                           const float* __restrict__ w2,
                           const float* __restrict__ b2,
                           float* __restrict__ out,
                           int nNodes)
{
    extern __shared__ float sm[];
    float* w1s    = sm;               // 32*128
    float* w2s    = w1s + NB * NA;    // 128*128
    float* b1s    = w2s + NA * NA;    // 128
    float* b2s    = b1s + NA;         // 128
    float* msg_in = b2s + NA;         // 32
    float* hidden = msg_in + NB;      // 128

    const int tid = threadIdx.x;
    for (int i = tid; i < NB * NA; i += blockDim.x) w1s[i] = w1[i];
    for (int i = tid; i < NA * NA; i += blockDim.x) w2s[i] = w2[i];
    if (tid < NA) { b1s[tid] = b1[tid]; b2s[tid] = b2[tid]; }
    __syncthreads();

    const int node0 = blockIdx.x * MSG_NPB;
    for (int i = 0; i < MSG_NPB; i++) {
        const int node = node0 + i;
        if (node >= nNodes) break;

        if (tid < NB) {
            const float* ap = &g_agg[node * (NT * NB) + tid];
            float f2 = 0.0f;
            #pragma unroll
            for (int t = 0; t < NT; t++) {
                float a = ap[t * NB];
                f2 = fmaf(a, a, f2);
            }
            float u = f2 + 1e-9f;
            float ss = u * u;
            #pragma unroll
            for (int off = 16; off > 0; off >>= 1)
                ss += __shfl_xor_sync(0xffffffffu, ss, off);
            const float invn = __fdividef(1.0f, sqrtf(ss) + 1.0f);
            msg_in[tid] = f2 * invn;
        }
        __syncthreads();

        float h = b1s[tid];
        #pragma unroll
        for (int b = 0; b < NB; b++)
            h = fmaf(msg_in[b], w1s[b * NA + tid], h);
        hidden[tid] = silu_fast(h);
        __syncthreads();

        float o = b2s[tid];
        #pragma unroll 16
        for (int k = 0; k < NA; k++)
            o = fmaf(hidden[k], w2s[k * NA + tid], o);
        out[node * NA + tid] = o;
        __syncthreads();
    }
}

// ---------------------------------------------------------------------------
extern "C" void kernel_launch(void* const* d_in, const int* in_sizes, int n_in,
                              void* d_out, int out_size)
{
    const float* feat    = (const float*)d_in[0];
    const float* dis_vec = (const float*)d_in[1];
    const float* cj_w1   = (const float*)d_in[2];
    const float* cj_b1   = (const float*)d_in[3];
    const float* cj_w2   = (const float*)d_in[4];
    const float* cj_b2   = (const float*)d_in[5];
    const float* msg_w1  = (const float*)d_in[6];
    const float* msg_b1  = (const float*)d_in[7];
    const float* msg_w2  = (const float*)d_in[8];
    const float* msg_b2  = (const float*)d_in[9];
    const float* filt_w1 = (const float*)d_in[10];
    const float* filt_w2 = (const float*)d_in[11];
    const float* filt_b2 = (const float*)d_in[12];
    const int*   src     = (const int*)d_in[13];
    const int*   dst     = (const int*)d_in[14];

    const int nNodes = in_sizes[0] / NA;
    const int nEdges = in_sizes[1] / 3;

    float* out_msg  = (float*)d_out;                      // [N, 128]
    float* out_filt = (float*)d_out + (size_t)nNodes * NA; // [E, 32]

    // smem sizes
    const int cj_smem  = (NA * NA + NA + NA + NA + 4) * sizeof(float);
    const int msg_smem = (NB * NA + NA * NA + NA + NA + NB + NA) * sizeof(float);
    cudaFuncSetAttribute(cj_kernel,  cudaFuncAttributeMaxDynamicSharedMemorySize, cj_smem);
    cudaFuncSetAttribute(msg_kernel, cudaFuncAttributeMaxDynamicSharedMemorySize, msg_smem);

    // 1) zero agg scratch
    zero_agg_kernel<<<1024, 256>>>();

    // 2) cj MLP
    {
        int blocks = (nNodes + CJ_NPB - 1) / CJ_NPB;
        cj_kernel<<<blocks, NA, cj_smem>>>(feat, cj_w1, cj_b1, cj_w2, cj_b2, nNodes);
    }

    // 3) edge kernel: one warp per edge
    {
        const int threads = 256;
        const int warps_per_block = threads / 32;
        int blocks = (nEdges + warps_per_block - 1) / warps_per_block;
        edge_kernel<<<blocks, threads>>>(dis_vec, src, dst, filt_w1, filt_w2, filt_b2,
                                         out_filt, nEdges);
    }

    // 4) msg MLP
    {
        int blocks = (nNodes + MSG_NPB - 1) / MSG_NPB;
        msg_kernel<<<blocks, NA, msg_smem>>>(msg_w1, msg_b1, msg_w2, msg_b2,
                                             out_msg, nNodes);
    }
}

// round 2
// speedup vs baseline: 2.0306x; 2.0306x over previous
#include <cuda_runtime.h>
#include <math.h>

#define NN 50000
#define NE 800000
#define NB 32
#define NT 6
#define NA 128
#define NPAD 50176            // 98 * 512, covers NN+1
#define NSCAN_BLK 98

// ---- static device scratch (no allocation) ----
__device__ int   g_cnt[NPAD];
__device__ int   g_ptr[NPAD];
__device__ int   g_fill[NPAD];
__device__ int   g_elist[NE];
__device__ int   g_bsum[NSCAN_BLK];
__device__ float g_cj[NN];
__device__ float g_msgin[NN * NB];

__device__ __forceinline__ float coeff_const() {
    constexpr float WF  = 10.0f / 31.0f;
    constexpr float W2F = WF * WF;
    constexpr double C  = -0.5 / (double)W2F;
    return (float)C;
}
__device__ __forceinline__ float silu_fast(float x) {
    return __fdividef(x, 1.0f + __expf(-x));
}

// ---------------------------------------------------------------------------
__global__ void zero_cnt_kernel() {
    int i = blockIdx.x * 512 + threadIdx.x;
    g_cnt[i] = 0;
}

__global__ void count_kernel(const int* __restrict__ src, int nEdges) {
    int i = blockIdx.x * blockDim.x + threadIdx.x;
    if (i < nEdges) atomicAdd(&g_cnt[src[i]], 1);
}

// block sums of g_cnt (512 per block)
__global__ void scan1_kernel() {
    __shared__ int ws[16];
    int t = threadIdx.x;
    int v = g_cnt[blockIdx.x * 512 + t];
    #pragma unroll
    for (int off = 16; off > 0; off >>= 1) v += __shfl_xor_sync(0xffffffffu, v, off);
    if ((t & 31) == 0) ws[t >> 5] = v;
    __syncthreads();
    if (t < 16) {
        int s = ws[t];
        #pragma unroll
        for (int off = 8; off > 0; off >>= 1) s += __shfl_xor_sync(0xffffu, s, off);
        if (t == 0) g_bsum[blockIdx.x] = s;
    }
}

// exclusive scan of the 98 block sums (serial, tiny)
__global__ void scan2_kernel() {
    if (threadIdx.x == 0) {
        int run = 0;
        for (int b = 0; b < NSCAN_BLK; b++) {
            int v = g_bsum[b];
            g_bsum[b] = run;
            run += v;
        }
    }
}

// per-block exclusive scan -> g_ptr, g_fill
__global__ void scan3_kernel() {
    __shared__ int s[512];
    int t = threadIdx.x;
    int i = blockIdx.x * 512 + t;
    int v = g_cnt[i];
    s[t] = v;
    __syncthreads();
    #pragma unroll
    for (int off = 1; off < 512; off <<= 1) {
        int x = (t >= off) ? s[t - off] : 0;
        __syncthreads();
        s[t] += x;
        __syncthreads();
    }
    int excl = s[t] - v + g_bsum[blockIdx.x];
    g_ptr[i]  = excl;
    g_fill[i] = excl;
}

__global__ void scatter_kernel(const int* __restrict__ src, int nEdges) {
    int i = blockIdx.x * blockDim.x + threadIdx.x;
    if (i < nEdges) {
        int s = src[i];
        int pos = atomicAdd(&g_fill[s], 1);
        g_elist[pos] = i;
    }
}

// ---------------------------------------------------------------------------
// cj = silu(feat @ w1 + b1) @ w2 + b2 -> g_cj
// 256 thr / 64 nodes per block; 8-node x 4-col register tile per thread.
__global__ void cj_kernel2(const float* __restrict__ feat,
                           const float* __restrict__ w1,
                           const float* __restrict__ b1,
                           const float* __restrict__ w2,
                           const float* __restrict__ b2,
                           int nNodes)
{
    __shared__ float sfeat[64 * NA];
    const int tid  = threadIdx.x;
    const int warp = tid >> 5;
    const int lane = tid & 31;
    const int node0 = blockIdx.x * 64;

    // load feat tile [64][128], guarded
    {
        float4* s4 = (float4*)sfeat;
        const float4* f4 = (const float4*)feat;
        for (int i = tid; i < 64 * (NA / 4); i += 256) {
            int n = node0 + i / (NA / 4);
            float4 v = make_float4(0.f, 0.f, 0.f, 0.f);
            if (n < nNodes) v = __ldg(&f4[(size_t)n * (NA / 4) + (i % (NA / 4))]);
            s4[i] = v;
        }
    }
    __syncthreads();

    const int c4 = lane * 4;
    float acc[8][4];
    #pragma unroll
    for (int i = 0; i < 8; i++)
        #pragma unroll
        for (int j = 0; j < 4; j++) acc[i][j] = 0.0f;

    const float* frow = &sfeat[warp * 8 * NA];
    #pragma unroll 4
    for (int k = 0; k < NA; k++) {
        float4 wv = __ldg((const float4*)(w1 + k * NA + c4));
        #pragma unroll
        for (int i = 0; i < 8; i++) {
            float f = frow[i * NA + k];
            acc[i][0] = fmaf(f, wv.x, acc[i][0]);
            acc[i][1] = fmaf(f, wv.y, acc[i][1]);
            acc[i][2] = fmaf(f, wv.z, acc[i][2]);
            acc[i][3] = fmaf(f, wv.w, acc[i][3]);
        }
    }

    float4 b1v = __ldg((const float4*)(b1 + c4));
    float4 w2v = __ldg((const float4*)(w2 + c4));
    float p[8];
    #pragma unroll
    for (int i = 0; i < 8; i++) {
        float h0 = silu_fast(acc[i][0] + b1v.x);
        float h1 = silu_fast(acc[i][1] + b1v.y);
        float h2 = silu_fast(acc[i][2] + b1v.z);
        float h3 = silu_fast(acc[i][3] + b1v.w);
        p[i] = h0 * w2v.x + h1 * w2v.y + h2 * w2v.z + h3 * w2v.w;
    }
    #pragma unroll
    for (int i = 0; i < 8; i++) {
        #pragma unroll
        for (int off = 16; off > 0; off >>= 1)
            p[i] += __shfl_xor_sync(0xffffffffu, p[i], off);
    }
    if (lane == 0) {
        float bb = __ldg(b2);
        #pragma unroll
        for (int i = 0; i < 8; i++) {
            int n = node0 + warp * 8 + i;
            if (n < nNodes) g_cj[n] = p[i] + bb;
        }
    }
}

// ---------------------------------------------------------------------------
// gather: warp per node; lane = basis. Recompute gaussian per edge, accumulate
// acc_t, then f2 -> normalized msg_in.
__global__ void gather_kernel(const float* __restrict__ dis_vec,
                              const int*   __restrict__ dst,
                              int nNodes)
{
    const int tid  = threadIdx.x;
    const int lane = tid & 31;
    const int node = blockIdx.x * 8 + (tid >> 5);
    if (node >= nNodes) return;

    const int start = g_ptr[node];
    const int end   = g_ptr[node + 1];

    const float off = (float)((double)lane * (10.0 / 31.0));
    const float C   = coeff_const();
    const float SQ2 = 1.41421356237309515f;

    float a0 = 0.f, a1 = 0.f, a2 = 0.f, a3 = 0.f, a4 = 0.f, a5 = 0.f;

    for (int base = start; base < end; base += 32) {
        int idx = base + lane;
        float vx = 0.f, vy = 0.f, vz = 0.f, c = 0.f, dis_l = 0.f;
        if (idx < end) {
            int e = g_elist[idx];
            vx = __ldg(&dis_vec[3 * e + 0]);
            vy = __ldg(&dis_vec[3 * e + 1]);
            vz = __ldg(&dis_vec[3 * e + 2]);
            c  = __ldg(&g_cj[__ldg(&dst[e])]);
            float dx = vx + 1e-9f, dy = vy + 1e-9f, dz = vz + 1e-9f;
            dis_l = sqrtf(fmaf(dx, dx, fmaf(dy, dy, dz * dz)));
        }
        int m = end - base; if (m > 32) m = 32;
        for (int j = 0; j < m; j++) {
            float bx = __shfl_sync(0xffffffffu, vx, j);
            float by = __shfl_sync(0xffffffffu, vy, j);
            float bz = __shfl_sync(0xffffffffu, vz, j);
            float bc = __shfl_sync(0xffffffffu, c,  j);
            float bd = __shfl_sync(0xffffffffu, dis_l, j);

            float x = bx + 1e-8f, y = by + 1e-8f, z = bz + 1e-8f;
            float dd = bd - off;
            float g0 = __expf(C * dd * dd);
            float w  = g0 * bc;

            a0 = fmaf(z * z,         w, a0);
            a1 = fmaf(SQ2 * (y * z), w, a1);
            a2 = fmaf(y * y,         w, a2);
            a3 = fmaf(SQ2 * (x * z), w, a3);
            a4 = fmaf(SQ2 * (x * y), w, a4);
            a5 = fmaf(x * x,         w, a5);
        }
    }

    float f2 = a0 * a0;
    f2 = fmaf(a1, a1, f2); f2 = fmaf(a2, a2, f2);
    f2 = fmaf(a3, a3, f2); f2 = fmaf(a4, a4, f2); f2 = fmaf(a5, a5, f2);

    float u = f2 + 1e-9f;
    float ss = u * u;
    #pragma unroll
    for (int o = 16; o > 0; o >>= 1)
        ss += __shfl_xor_sync(0xffffffffu, ss, o);
    float invn = __fdividef(1.0f, sqrtf(ss) + 1.0f);
    g_msgin[node * NB + lane] = f2 * invn;
}

// ---------------------------------------------------------------------------
// msg MLP: silu(msg_in @ w1 + b1) @ w2 + b2 -> out[n][128]
__global__ void msg_kernel2(const float* __restrict__ w1,
                            const float* __restrict__ b1,
                            const float* __restrict__ w2,
                            const float* __restrict__ b2,
                            float* __restrict__ out,
                            int nNodes)
{
    extern __shared__ float sm[];
    float* w1s = sm;                 // [32][128]
    float* mi  = w1s + NB * NA;      // [64][32]
    float* hid = mi + 64 * NB;       // [64][128]

    const int tid  = threadIdx.x;
    const int warp = tid >> 5;
    const int lane = tid & 31;
    const int node0 = blockIdx.x * 64;

    for (int i = tid; i < NB * NA / 4; i += 256)
        ((float4*)w1s)[i] = __ldg(&((const float4*)w1)[i]);
    for (int i = tid; i < 64 * NB / 4; i += 256) {
        int n = node0 + i / (NB / 4);
        float4 v = make_float4(0.f, 0.f, 0.f, 0.f);
        if (n < nNodes) v = ((const float4*)g_msgin)[(size_t)n * (NB / 4) + (i % (NB / 4))];
        ((float4*)mi)[i] = v;
    }
    __syncthreads();

    const int c4 = lane * 4;
    float acc[8][4];
    #pragma unroll
    for (int i = 0; i < 8; i++)
        #pragma unroll
        for (int j = 0; j < 4; j++) acc[i][j] = 0.0f;

    // Phase A: hidden = silu(mi @ w1 + b1)
    const float* mrow = &mi[warp * 8 * NB];
    #pragma unroll 4
    for (int b = 0; b < NB; b++) {
        float4 wv = *(const float4*)(w1s + b * NA + c4);
        #pragma unroll
        for (int i = 0; i < 8; i++) {
            float f = mrow[i * NB + b];
            acc[i][0] = fmaf(f, wv.x, acc[i][0]);
            acc[i][1] = fmaf(f, wv.y, acc[i][1]);
            acc[i][2] = fmaf(f, wv.z, acc[i][2]);
            acc[i][3] = fmaf(f, wv.w, acc[i][3]);
        }
    }
    {
        float4 b1v = __ldg((const float4*)(b1 + c4));
        #pragma unroll
        for (int i = 0; i < 8; i++) {
            float4 h;
            h.x = silu_fast(acc[i][0] + b1v.x);
            h.y = silu_fast(acc[i][1] + b1v.y);
            h.z = silu_fast(acc[i][2] + b1v.z);
            h.w = silu_fast(acc[i][3] + b1v.w);
            *(float4*)(hid + (warp * 8 + i) * NA + c4) = h;
        }
    }
    __syncthreads();

    // Phase B: out = hidden @ w2 + b2
    #pragma unroll
    for (int i = 0; i < 8; i++)
        #pragma unroll
        for (int j = 0; j < 4; j++) acc[i][j] = 0.0f;

    const float* hrow = &hid[warp * 8 * NA];
    #pragma unroll 4
    for (int k = 0; k < NA; k++) {
        float4 wv = __ldg((const float4*)(w2 + k * NA + c4));
        #pragma unroll
        for (int i = 0; i < 8; i++) {
            float f = hrow[i * NA + k];
            acc[i][0] = fmaf(f, wv.x, acc[i][0]);
            acc[i][1] = fmaf(f, wv.y, acc[i][1]);
            acc[i][2] = fmaf(f, wv.z, acc[i][2]);
            acc[i][3] = fmaf(f, wv.w, acc[i][3]);
        }
    }
    float4 b2v = __ldg((const float4*)(b2 + c4));
    #pragma unroll
    for (int i = 0; i < 8; i++) {
        int n = node0 + warp * 8 + i;
        if (n < nNodes) {
            float4 o;
            o.x = acc[i][0] + b2v.x;
            o.y = acc[i][1] + b2v.y;
            o.z = acc[i][2] + b2v.z;
            o.w = acc[i][3] + b2v.w;
            *(float4*)(out + (size_t)n * NA + c4) = o;
        }
    }
}

// ---------------------------------------------------------------------------
// filt kernel: one warp per edge, lane = basis. No atomics.
__global__ void filt_kernel(const float* __restrict__ dis_vec,
                            const float* __restrict__ fw1,
                            const float* __restrict__ fw2,
                            const float* __restrict__ fb2,
                            float* __restrict__ filt_out,
                            int nEdges)
{
    __shared__ float sW1[36];
    __shared__ float sW2[6];
    __shared__ float sB2;

    const int tid = threadIdx.x;
    if (tid < 36) sW1[tid] = fw1[tid];
    if (tid < 6)  sW2[tid] = fw2[tid];
    if (tid == 36) sB2 = fb2[0];
    __syncthreads();

    const int e    = (blockIdx.x * blockDim.x + tid) >> 5;
    const int lane = tid & 31;
    if (e >= nEdges) return;

    const float vx = __ldg(&dis_vec[3 * e + 0]);
    const float vy = __ldg(&dis_vec[3 * e + 1]);
    const float vz = __ldg(&dis_vec[3 * e + 2]);

    const float x = vx + 1e-8f, y = vy + 1e-8f, z = vz + 1e-8f;
    const float SQ2 = 1.41421356237309515f;
    const float q0 = z * z;
    const float q1 = SQ2 * (y * z);
    const float q2 = y * y;
    const float q3 = SQ2 * (x * z);
    const float q4 = SQ2 * (x * y);
    const float q5 = x * x;

    const float dx = vx + 1e-9f, dy = vy + 1e-9f, dz = vz + 1e-9f;
    const float dis = sqrtf(fmaf(dx, dx, fmaf(dy, dy, dz * dz)));
    const float off = (float)((double)lane * (10.0 / 31.0));
    const float dd  = dis - off;
    const float g0  = __expf(coeff_const() * dd * dd);

    const float ga0 = q0 * g0, ga1 = q1 * g0, ga2 = q2 * g0;
    const float ga3 = q3 * g0, ga4 = q4 * g0, ga5 = q5 * g0;

    const float v0 = ga0 + 1e-8f, v1 = ga1 + 1e-8f, v2 = ga2 + 1e-8f;
    const float v3 = ga3 + 1e-8f, v4 = ga4 + 1e-8f, v5 = ga5 + 1e-8f;
    float nn = v0 * v0;
    nn = fmaf(v1, v1, nn); nn = fmaf(v2, v2, nn);
    nn = fmaf(v3, v3, nn); nn = fmaf(v4, v4, nn); nn = fmaf(v5, v5, nn);
    const float sq  = nn * __frsqrt_rn(nn);
    const float inv = __fdividef(1.0f, sq + 1.0f);

    float r = 0.0f;
    #pragma unroll
    for (int j = 0; j < 6; j++) {
        float h = ga0 * sW1[0 * 6 + j];
        h = fmaf(ga1, sW1[1 * 6 + j], h);
        h = fmaf(ga2, sW1[2 * 6 + j], h);
        h = fmaf(ga3, sW1[3 * 6 + j], h);
        h = fmaf(ga4, sW1[4 * 6 + j], h);
        h = fmaf(ga5, sW1[5 * 6 + j], h);
        h *= inv;
        r = fmaf(silu_fast(h), sW2[j], r);
    }
    filt_out[e * NB + lane] = r + sB2;
}

// ---------------------------------------------------------------------------
extern "C" void kernel_launch(void* const* d_in, const int* in_sizes, int n_in,
                              void* d_out, int out_size)
{
    const float* feat    = (const float*)d_in[0];
    const float* dis_vec = (const float*)d_in[1];
    const float* cj_w1   = (const float*)d_in[2];
    const float* cj_b1   = (const float*)d_in[3];
    const float* cj_w2   = (const float*)d_in[4];
    const float* cj_b2   = (const float*)d_in[5];
    const float* msg_w1  = (const float*)d_in[6];
    const float* msg_b1  = (const float*)d_in[7];
    const float* msg_w2  = (const float*)d_in[8];
    const float* msg_b2  = (const float*)d_in[9];
    const float* filt_w1 = (const float*)d_in[10];
    const float* filt_w2 = (const float*)d_in[11];
    const float* filt_b2 = (const float*)d_in[12];
    const int*   src     = (const int*)d_in[13];
    const int*   dst     = (const int*)d_in[14];

    const int nNodes = in_sizes[0] / NA;
    const int nEdges = in_sizes[1] / 3;

    float* out_msg  = (float*)d_out;
    float* out_filt = (float*)d_out + (size_t)nNodes * NA;

    const int msg_smem = (NB * NA + 64 * NB + 64 * NA) * sizeof(float); // 57344
    cudaFuncSetAttribute(msg_kernel2, cudaFuncAttributeMaxDynamicSharedMemorySize, msg_smem);

    // CSR build
    zero_cnt_kernel<<<NSCAN_BLK, 512>>>();
    count_kernel<<<(nEdges + 255) / 256, 256>>>(src, nEdges);
    scan1_kernel<<<NSCAN_BLK, 512>>>();
    scan2_kernel<<<1, 32>>>();
    scan3_kernel<<<NSCAN_BLK, 512>>>();
    scatter_kernel<<<(nEdges + 255) / 256, 256>>>(src, nEdges);

    // cj MLP
    cj_kernel2<<<(nNodes + 63) / 64, 256>>>(feat, cj_w1, cj_b1, cj_w2, cj_b2, nNodes);

    // gather (agg + f2 + normalize)
    gather_kernel<<<(nNodes + 7) / 8, 256>>>(dis_vec, dst, nNodes);

    // msg MLP
    msg_kernel2<<<(nNodes + 63) / 64, 256, msg_smem>>>(msg_w1, msg_b1, msg_w2, msg_b2,
                                                       out_msg, nNodes);

    // filt (independent of everything above)
    filt_kernel<<<(nEdges * 32 + 255) / 256, 256>>>(dis_vec, filt_w1, filt_w2, filt_b2,
                                                    out_filt, nEdges);
}